// round 9
// baseline (speedup 1.0000x reference)
#include <cuda_runtime.h>
#include <cuda_fp16.h>
#include <cstdint>

// ===========================================================================
// ConstraintDecoderModel — fp16 mma.sync + bulk-copy pipeline, R9:
//  * os2 re-tiled 64x128 (256 CTAs, 3 CTAs/SM) — R8 showed os2 latency-bound
//    at 8 warps/SM (tensor 38%, issue 17%).
//  * stream-forked launch graph: build_dir || wexp; heads || (os2 -> logits).
// Operands stored pre-swizzled in chunk-contiguous 16KB blocks (smem image).
// ===========================================================================

#define NROWS 4096

// ---------------- scratch (device globals; no allocation allowed) ----------
__device__ __align__(128) __half g_dir [NROWS * 2048];  // blocked, NCh=32
__device__ __align__(128) __half g_h1os[NROWS * 1024];  // blocked, NCh=16
__device__ __align__(128) __half g_h1ct[NROWS * 1024];  // linear fp16
__device__ __align__(128) __half g_h1ds[NROWS * 1024];  // linear fp16
__device__ __align__(128) float  g_ptr [NROWS * 512];   // linear f32
__device__ __align__(128) __half g_w_ct [1024 *  512];  // blocked, NCh=8
__device__ __align__(128) __half g_w_os1[1024 * 1536];  // blocked, NCh=24
__device__ __align__(128) __half g_w_os2[ 512 * 1024];  // blocked, NCh=16
__device__ __align__(128) __half g_w_ds [1024 * 2048];  // blocked, NCh=32

// ---------------- helpers ---------------------------------------------------
__device__ __forceinline__ uint32_t smem_u32(const void* p) {
    uint32_t a;
    asm("{ .reg .u64 t; cvta.to.shared.u64 t, %1; cvt.u32.u64 %0, t; }"
        : "=r"(a) : "l"(p));
    return a;
}
__device__ __forceinline__ void ldsm_x4(uint32_t& r0, uint32_t& r1,
                                        uint32_t& r2, uint32_t& r3, uint32_t addr) {
    asm volatile("ldmatrix.sync.aligned.m8n8.x4.shared.b16 {%0,%1,%2,%3}, [%4];"
                 : "=r"(r0), "=r"(r1), "=r"(r2), "=r"(r3) : "r"(addr));
}
__device__ __forceinline__ void mma_f16(float* d, const uint32_t* a,
                                        uint32_t b0, uint32_t b1) {
    asm volatile(
        "mma.sync.aligned.m16n8k16.row.col.f32.f16.f16.f32 "
        "{%0,%1,%2,%3}, {%4,%5,%6,%7}, {%8,%9}, {%0,%1,%2,%3};"
        : "+f"(d[0]), "+f"(d[1]), "+f"(d[2]), "+f"(d[3])
        : "r"(a[0]), "r"(a[1]), "r"(a[2]), "r"(a[3]), "r"(b0), "r"(b1));
}
#define MBAR_INIT(a, c) \
    asm volatile("mbarrier.init.shared.b64 [%0], %1;" :: "r"((uint32_t)(a)), "r"((uint32_t)(c)) : "memory")
#define MBAR_EXPECT_TX(a, tx) \
    asm volatile("mbarrier.arrive.expect_tx.shared.b64 _, [%0], %1;" :: "r"((uint32_t)(a)), "r"((uint32_t)(tx)) : "memory")
#define MBAR_WAIT_PARITY(addr, par) do { \
    uint32_t _m = (uint32_t)(addr); uint32_t _p = (uint32_t)(par); uint32_t _d; \
    asm volatile("{\n\t.reg .pred p;\n\t" \
        "mbarrier.try_wait.parity.acquire.cta.shared::cta.b64 p, [%1], %2;\n\t" \
        "selp.b32 %0, 1, 0, p;\n\t}" : "=r"(_d) : "r"(_m), "r"(_p) : "memory"); \
    if (!_d) { \
        asm volatile("{\n\t.reg .pred P1;\n\t" \
            "WL_%=:\n\t" \
            "mbarrier.try_wait.parity.acquire.cta.shared::cta.b64 P1, [%0], %1, 0x989680;\n\t" \
            "@P1 bra.uni WD_%=;\n\t" \
            "bra.uni WL_%=;\n\t" \
            "WD_%=:\n\t}" :: "r"(_m), "r"(_p) : "memory"); \
    } } while (0)
#define FENCE_PROXY_ASYNC() asm volatile("fence.proxy.async.shared::cta;" ::: "memory")
__device__ __forceinline__ void bulk_g2s(uint32_t dst, const void* src,
                                         uint32_t bytes, uint32_t mbar) {
    asm volatile(
        "cp.async.bulk.shared::cluster.global.mbarrier::complete_tx::bytes "
        "[%0], [%1], %2, [%3];"
        :: "r"(dst), "l"(src), "r"(bytes), "r"(mbar) : "memory");
}

// swizzle within a 16KB block: row r, 16B-group c (0..7)
__device__ __forceinline__ uint32_t swz(uint32_t r, uint32_t c) {
    return r * 128 + ((c ^ (r & 7)) << 4);
}
__device__ __forceinline__ uint32_t blk_elem(uint32_t r, uint32_t h) {
    return swz(r, h >> 3) + (h & 7) * 2;
}

// ---------------------------------------------------------------------------
// build dir (blocked): row n gets [heads|type|q|r], K=2048, NCh=32.
// ---------------------------------------------------------------------------
__global__ __launch_bounds__(128) void build_dir_kernel(
    const float* __restrict__ dec, const float* __restrict__ src,
    const int* __restrict__ tgt_c, const float* __restrict__ type_emb)
{
    int n = blockIdx.x;
    int b = n & 63;
    int t0 = tgt_c[n * 3 + 0];
    int q  = tgt_c[n * 3 + 1];
    int r  = tgt_c[n * 3 + 2];
    const float* segs[4] = {
        dec + (size_t)n * 512,
        type_emb + (size_t)t0 * 512,
        src + ((size_t)q * 64 + b) * 512,
        src + ((size_t)r * 64 + b) * 512 };
    char* base = (char*)g_dir + (size_t)(n >> 7) * 32 * 16384;
    uint32_t rr = n & 127;
#pragma unroll
    for (int s = 0; s < 4; s++) {
        const float* P = segs[s];
        for (int i = threadIdx.x * 2; i < 512; i += 256) {
            float2 v = *reinterpret_cast<const float2*>(P + i);
            int kk = s * 512 + i;
            char* dst = base + (size_t)(kk >> 6) * 16384 + blk_elem(rr, kk & 63);
            *reinterpret_cast<__half2*>(dst) =
                __halves2half2(__float2half_rn(v.x), __float2half_rn(v.y));
        }
    }
}

// ---------------------------------------------------------------------------
// Merged weight transpose+convert into BLOCKED fp16 layouts.
// ---------------------------------------------------------------------------
__global__ __launch_bounds__(256) void wexp_all_kernel(
    const float* __restrict__ Wct,  const float* __restrict__ Wos1,
    const float* __restrict__ Wos2, const float* __restrict__ Wds)
{
    int g = blockIdx.x;
    const float* W;
    __half* out;
    int K, N, loc, NCh;
    if (g < 512)       { W = Wct;  out = g_w_ct;  K =  512; N = 1024; loc = g;        NCh =  8; }
    else if (g < 2048) { W = Wos1; out = g_w_os1; K = 1536; N = 1024; loc = g - 512;  NCh = 24; }
    else if (g < 2560) { W = Wos2; out = g_w_os2; K = 1024; N =  512; loc = g - 2048; NCh = 16; }
    else               { W = Wds;  out = g_w_ds;  K = 2048; N = 1024; loc = g - 2560; NCh = 32; }
    int nx = N >> 5;
    int n0 = (loc % nx) * 32, k0 = (loc / nx) * 32;

    __shared__ float t[32][33];
    int tx = threadIdx.x & 31;
    int ty = threadIdx.x >> 5;
#pragma unroll
    for (int r = 0; r < 4; r++)
        t[ty + r * 8][tx] = W[(size_t)(k0 + ty + r * 8) * N + n0 + tx];
    __syncthreads();
#pragma unroll
    for (int r = 0; r < 4; r++) {
        int n = n0 + ty + r * 8;
        int k = k0 + tx;
        char* dst = (char*)out +
            (size_t)((n >> 7) * NCh + (k >> 6)) * 16384 + blk_elem(n & 127, k & 63);
        *reinterpret_cast<__half*>(dst) = __float2half_rn(t[tx][ty + r * 8]);
    }
}

// ---------------------------------------------------------------------------
// 128x128 GEMM body (fused3), bulk-copy pipeline, 3x32KB stages.
// outmode 1: fp16 BLOCKED (NCh=ldc/64); 2: fp16 linear.
// ---------------------------------------------------------------------------
#define STAGES 3
#define STAGE_B 32768
#define GEMM_SMEM (STAGES * STAGE_B + 64)

__device__ __forceinline__ void gemm_body(
    const char* __restrict__ Ab, int sA,
    const char* __restrict__ Bb, int sB,
    const float* __restrict__ bias, void* __restrict__ Cout, int ldc,
    int NC, int bmt, int bnt, int outmode, char* smem)
{
    const uint32_t sbase = smem_u32(smem);
    const uint32_t mb = sbase + STAGES * STAGE_B;
    const int tid = threadIdx.x;
    const int wid = tid >> 5;
    const int lane = tid & 31;
    const int wm = (wid & 3) * 32;
    const int wn = (wid >> 2) * 64;

    if (tid == 0) {
#pragma unroll
        for (int s = 0; s < STAGES; s++) MBAR_INIT(mb + 8 * s, 1);
    }
    __syncthreads();
    FENCE_PROXY_ASYNC();

    auto issue = [&](int c) {
        int sl = c % STAGES;
        uint32_t dst = sbase + sl * STAGE_B;
        MBAR_EXPECT_TX(mb + 8 * sl, 32768);
        bulk_g2s(dst,         Ab + (size_t)(bmt * sA + c) * 16384, 16384, mb + 8 * sl);
        bulk_g2s(dst + 16384, Bb + (size_t)(bnt * sB + c) * 16384, 16384, mb + 8 * sl);
    };
    if (tid == 0) { issue(0); issue(1); }

    float acc[2][8][4];
#pragma unroll
    for (int i = 0; i < 2; i++)
#pragma unroll
        for (int j = 0; j < 8; j++)
#pragma unroll
            for (int v = 0; v < 4; v++) acc[i][j][v] = 0.f;

    const int a_r  = lane & 15;
    const int a_cb = lane >> 4;
    const int b_r  = ((lane >> 4) << 3) + (lane & 7);
    const int b_cb = (lane >> 3) & 1;

    for (int c = 0; c < NC; c++) {
        int sl = c % STAGES;
        MBAR_WAIT_PARITY(mb + 8 * sl, (c / STAGES) & 1);
        __syncthreads();
        if (tid == 0 && c + 2 < NC) issue(c + 2);

        uint32_t As = sbase + sl * STAGE_B;
        uint32_t Bs = As + 16384;
#pragma unroll
        for (int ks = 0; ks < 4; ks++) {
            uint32_t a[2][4];
#pragma unroll
            for (int mi = 0; mi < 2; mi++)
                ldsm_x4(a[mi][0], a[mi][1], a[mi][2], a[mi][3],
                        As + swz(wm + mi * 16 + a_r, ks * 2 + a_cb));
            uint32_t b[4][4];
#pragma unroll
            for (int ni = 0; ni < 4; ni++)
                ldsm_x4(b[ni][0], b[ni][1], b[ni][2], b[ni][3],
                        Bs + swz(wn + ni * 16 + b_r, ks * 2 + b_cb));
#pragma unroll
            for (int mi = 0; mi < 2; mi++)
#pragma unroll
                for (int n8 = 0; n8 < 8; n8++)
                    mma_f16(acc[mi][n8], a[mi],
                            b[n8 >> 1][(n8 & 1) * 2], b[n8 >> 1][(n8 & 1) * 2 + 1]);
        }
    }

    const int bm = bmt * 128, bn = bnt * 128;
#pragma unroll
    for (int mi = 0; mi < 2; mi++) {
        int r0 = bm + wm + mi * 16 + (lane >> 2);
#pragma unroll
        for (int n8 = 0; n8 < 8; n8++) {
            int col = bn + wn + n8 * 8 + (lane & 3) * 2;
            float b0 = bias[col], b1 = bias[col + 1];
            float v00 = acc[mi][n8][0] + b0;
            float v01 = acc[mi][n8][1] + b1;
            float v10 = acc[mi][n8][2] + b0;
            float v11 = acc[mi][n8][3] + b1;
            v00 = v00 > 0.f ? v00 : 0.01f * v00;
            v01 = v01 > 0.f ? v01 : 0.01f * v01;
            v10 = v10 > 0.f ? v10 : 0.01f * v10;
            v11 = v11 > 0.f ? v11 : 0.01f * v11;
            if (outmode == 1) {
                int NCh = ldc >> 6;
                char* C = (char*)Cout;
                char* d0 = C + (size_t)((r0 >> 7) * NCh + (col >> 6)) * 16384
                             + blk_elem(r0 & 127, col & 63);
                *reinterpret_cast<__half2*>(d0) =
                    __halves2half2(__float2half_rn(v00), __float2half_rn(v01));
                int r1 = r0 + 8;
                char* d1 = C + (size_t)((r1 >> 7) * NCh + (col >> 6)) * 16384
                             + blk_elem(r1 & 127, col & 63);
                *reinterpret_cast<__half2*>(d1) =
                    __halves2half2(__float2half_rn(v10), __float2half_rn(v11));
            } else {
                __half* C = (__half*)Cout;
                *reinterpret_cast<__half2*>(C + (size_t)r0 * ldc + col) =
                    __halves2half2(__float2half_rn(v00), __float2half_rn(v01));
                *reinterpret_cast<__half2*>(C + (size_t)(r0 + 8) * ldc + col) =
                    __halves2half2(__float2half_rn(v10), __float2half_rn(v11));
            }
        }
    }
}

__global__ __launch_bounds__(256, 2) void gemm_fused3(
    const float* __restrict__ ds_b1,
    const float* __restrict__ os_b1,
    const float* __restrict__ ct_b1)
{
    extern __shared__ char smem[];
    int g = blockIdx.x;
    int id = g >> 8, r = g & 255;
    int bmt = r >> 3, bnt = r & 7;
    if (id == 0)
        gemm_body((const char*)g_dir, 32, (const char*)g_w_ds, 32,
                  ds_b1, g_h1ds, 1024, 32, bmt, bnt, 2, smem);
    else if (id == 1)
        gemm_body((const char*)g_dir, 32, (const char*)g_w_os1, 24,
                  os_b1, g_h1os, 1024, 24, bmt, bnt, 1, smem);
    else
        gemm_body((const char*)g_dir, 32, (const char*)g_w_ct, 8,
                  ct_b1, g_h1ct, 1024, 8, bmt, bnt, 2, smem);
}

// ---------------------------------------------------------------------------
// os2: 64x128 tiles, grid (4, 64) = 256 CTAs, 3 CTAs/SM, no activation.
// A = g_h1os blocked NCh=16 (8KB half-blocks), B = g_w_os2 blocked NCh=16.
// Stage = 8KB A + 16KB B = 24KB; 3 stages.
// ---------------------------------------------------------------------------
#define OS2_STAGE 24576
#define OS2_SMEM (3 * OS2_STAGE + 64)

__global__ __launch_bounds__(256, 3) void gemm_os2(const float* __restrict__ os_b2)
{
    extern __shared__ char smem[];
    const uint32_t sbase = smem_u32(smem);
    const uint32_t mb = sbase + 3 * OS2_STAGE;
    const int tid = threadIdx.x;
    const int wid = tid >> 5;
    const int lane = tid & 31;
    const int wm = (wid & 1) * 32;          // 2 m-groups (64 rows)
    const int wn = (wid >> 1) * 32;         // 4 n-groups (128 cols)
    const int mt = blockIdx.y;              // 0..63
    const int nt = blockIdx.x;              // 0..3
    const int NC = 16;

    const char* Ab = (const char*)g_h1os;
    const char* Bb = (const char*)g_w_os2;

    if (tid == 0) {
#pragma unroll
        for (int s = 0; s < 3; s++) MBAR_INIT(mb + 8 * s, 1);
    }
    __syncthreads();
    FENCE_PROXY_ASYNC();

    auto issue = [&](int c) {
        int sl = c % 3;
        uint32_t dst = sbase + sl * OS2_STAGE;
        MBAR_EXPECT_TX(mb + 8 * sl, 24576);
        bulk_g2s(dst, Ab + (size_t)((mt >> 1) * 16 + c) * 16384 + (mt & 1) * 8192,
                 8192, mb + 8 * sl);
        bulk_g2s(dst + 8192, Bb + (size_t)(nt * 16 + c) * 16384, 16384, mb + 8 * sl);
    };
    if (tid == 0) { issue(0); issue(1); }

    float acc[2][4][4];
#pragma unroll
    for (int i = 0; i < 2; i++)
#pragma unroll
        for (int j = 0; j < 4; j++)
#pragma unroll
            for (int v = 0; v < 4; v++) acc[i][j][v] = 0.f;

    const int a_r  = lane & 15;
    const int a_cb = lane >> 4;
    const int b_r  = ((lane >> 4) << 3) + (lane & 7);
    const int b_cb = (lane >> 3) & 1;

    for (int c = 0; c < NC; c++) {
        int sl = c % 3;
        MBAR_WAIT_PARITY(mb + 8 * sl, (c / 3) & 1);
        __syncthreads();
        if (tid == 0 && c + 2 < NC) issue(c + 2);

        uint32_t As = sbase + sl * OS2_STAGE;
        uint32_t Bs = As + 8192;
#pragma unroll
        for (int ks = 0; ks < 4; ks++) {
            uint32_t a[2][4];
#pragma unroll
            for (int mi = 0; mi < 2; mi++)
                ldsm_x4(a[mi][0], a[mi][1], a[mi][2], a[mi][3],
                        As + swz(wm + mi * 16 + a_r, ks * 2 + a_cb));
            uint32_t b[2][4];
#pragma unroll
            for (int ni = 0; ni < 2; ni++)
                ldsm_x4(b[ni][0], b[ni][1], b[ni][2], b[ni][3],
                        Bs + swz(wn + ni * 16 + b_r, ks * 2 + b_cb));
#pragma unroll
            for (int mi = 0; mi < 2; mi++)
#pragma unroll
                for (int n8 = 0; n8 < 4; n8++)
                    mma_f16(acc[mi][n8], a[mi],
                            b[n8 >> 1][(n8 & 1) * 2], b[n8 >> 1][(n8 & 1) * 2 + 1]);
        }
    }

#pragma unroll
    for (int mi = 0; mi < 2; mi++) {
        int r0 = mt * 64 + wm + mi * 16 + (lane >> 2);
#pragma unroll
        for (int n8 = 0; n8 < 4; n8++) {
            int col = nt * 128 + wn + n8 * 8 + (lane & 3) * 2;
            float b0 = os_b2[col], b1 = os_b2[col + 1];
            g_ptr[(size_t)r0 * 512 + col]           = acc[mi][n8][0] + b0;
            g_ptr[(size_t)r0 * 512 + col + 1]       = acc[mi][n8][1] + b1;
            g_ptr[(size_t)(r0 + 8) * 512 + col]     = acc[mi][n8][2] + b0;
            g_ptr[(size_t)(r0 + 8) * 512 + col + 1] = acc[mi][n8][3] + b1;
        }
    }
}

// ---------------------------------------------------------------------------
// Tiny-N output heads (fp16 linear hidden in, f32 out).
// ---------------------------------------------------------------------------
template<int NOUT>
__device__ __forceinline__ void head_body(
    const __half* __restrict__ H, const float* __restrict__ W,
    const float* __restrict__ bias, float* __restrict__ out, int n)
{
    const __half* h = H + (size_t)n * 1024;
    float acc[NOUT];
#pragma unroll
    for (int c = 0; c < NOUT; c++) acc[c] = 0.f;
    for (int k = threadIdx.x * 2; k < 1024; k += 512) {
        __half2 hv = *reinterpret_cast<const __half2*>(h + k);
        float vx = __half2float(__low2half(hv));
        float vy = __half2float(__high2half(hv));
#pragma unroll
        for (int c = 0; c < NOUT; c++)
            acc[c] += vx * W[k * NOUT + c] + vy * W[(k + 1) * NOUT + c];
    }
#pragma unroll
    for (int c = 0; c < NOUT; c++)
#pragma unroll
        for (int off = 16; off > 0; off >>= 1)
            acc[c] += __shfl_xor_sync(0xffffffffu, acc[c], off);
    __shared__ float part[8][8];
    int warp = threadIdx.x >> 5, lane = threadIdx.x & 31;
    if (lane == 0)
#pragma unroll
        for (int c = 0; c < NOUT; c++) part[warp][c] = acc[c];
    __syncthreads();
    if (threadIdx.x == 0) {
#pragma unroll
        for (int c = 0; c < NOUT; c++) {
            float s = bias[c];
            for (int w = 0; w < 8; w++) s += part[w][c];
            out[(size_t)n * NOUT + c] = s;
        }
    }
}

__global__ __launch_bounds__(256) void heads_kernel(
    const float* __restrict__ ct_W2, const float* __restrict__ ct_b2,
    const float* __restrict__ ds_W2, const float* __restrict__ ds_b2,
    float* __restrict__ out_type, float* __restrict__ out_dir)
{
    int g = blockIdx.x;
    if (g < NROWS) head_body<4>(g_h1ct, ct_W2, ct_b2, out_type, g);
    else           head_body<5>(g_h1ds, ds_W2, ds_b2, out_dir, g - NROWS);
}

// ---------------------------------------------------------------------------
// Logits: C[t][s] (per b) = dot(ptr[t*64+b], src_e[s,b]) over 512.
// ---------------------------------------------------------------------------
__global__ __launch_bounds__(256) void logits_kernel(
    const float* __restrict__ src, float* __restrict__ out_obj)
{
    int tq = blockIdx.x;
    int b  = blockIdx.y;
    __shared__ float Ps[32][17];
    __shared__ float Ss[32][68];

    const int tid = threadIdx.x;
    const int ty = tid >> 4;
    const int tx = tid & 15;

    float acc[4] = {0.f, 0.f, 0.f, 0.f};

    for (int k0 = 0; k0 < 512; k0 += 32) {
        if (tid < 128) {
            int tl = tid >> 3, kc = tid & 7;
            float4 v = *reinterpret_cast<const float4*>(
                g_ptr + ((size_t)(tq * 16 + tl) * 64 + b) * 512 + k0 + kc * 4);
            Ps[kc * 4 + 0][tl] = v.x; Ps[kc * 4 + 1][tl] = v.y;
            Ps[kc * 4 + 2][tl] = v.z; Ps[kc * 4 + 3][tl] = v.w;
        }
#pragma unroll
        for (int i = 0; i < 2; i++) {
            int sl = tid + 256 * i;
            int s = sl >> 3, kc = sl & 7;
            float4 v = *reinterpret_cast<const float4*>(
                src + ((size_t)s * 64 + b) * 512 + k0 + kc * 4);
            Ss[kc * 4 + 0][s] = v.x; Ss[kc * 4 + 1][s] = v.y;
            Ss[kc * 4 + 2][s] = v.z; Ss[kc * 4 + 3][s] = v.w;
        }
        __syncthreads();
#pragma unroll
        for (int kk = 0; kk < 32; kk++) {
            float a = Ps[kk][ty];
            float4 br = *reinterpret_cast<const float4*>(&Ss[kk][tx * 4]);
            acc[0] += a * br.x;
            acc[1] += a * br.y;
            acc[2] += a * br.z;
            acc[3] += a * br.w;
        }
        __syncthreads();
    }

    float* crow = out_obj + ((size_t)(tq * 16 + ty) * 64 + b) * 64 + tx * 4;
    *reinterpret_cast<float4*>(crow) = make_float4(acc[0], acc[1], acc[2], acc[3]);
}

// ---------------------------------------------------------------------------
extern "C" void kernel_launch(void* const* d_in, const int* in_sizes, int n_in,
                              void* d_out, int out_size)
{
    const float* dec      = (const float*)d_in[0];
    const float* src      = (const float*)d_in[1];
    const int*   tgt_c    = (const int*)d_in[3];
    const float* type_emb = (const float*)d_in[6];
    const float* ct_W1 = (const float*)d_in[7];
    const float* ct_b1 = (const float*)d_in[8];
    const float* ct_W2 = (const float*)d_in[9];
    const float* ct_b2 = (const float*)d_in[10];
    const float* os_W1 = (const float*)d_in[11];
    const float* os_b1 = (const float*)d_in[12];
    const float* os_W2 = (const float*)d_in[13];
    const float* os_b2 = (const float*)d_in[14];
    const float* ds_W1 = (const float*)d_in[15];
    const float* ds_b1 = (const float*)d_in[16];
    const float* ds_W2 = (const float*)d_in[17];
    const float* ds_b2 = (const float*)d_in[18];

    float* out      = (float*)d_out;
    float* out_type = out;
    float* out_obj  = out + 4096 * 4;
    float* out_dir  = out + 4096 * 4 + 4096 * 64;

    cudaFuncSetAttribute(gemm_fused3, cudaFuncAttributeMaxDynamicSharedMemorySize, GEMM_SMEM);
    cudaFuncSetAttribute(gemm_os2,    cudaFuncAttributeMaxDynamicSharedMemorySize, OS2_SMEM);

    // One-time stream/event handles (host-side bookkeeping only; the device
    // work per call is identical and deterministic).
    static cudaStream_t s1 = [] {
        cudaStream_t s; cudaStreamCreateWithFlags(&s, cudaStreamNonBlocking); return s; }();
    static cudaEvent_t ev_fork = [] {
        cudaEvent_t e; cudaEventCreateWithFlags(&e, cudaEventDisableTiming); return e; }();
    static cudaEvent_t ev_bd = [] {
        cudaEvent_t e; cudaEventCreateWithFlags(&e, cudaEventDisableTiming); return e; }();
    static cudaEvent_t ev_f3 = [] {
        cudaEvent_t e; cudaEventCreateWithFlags(&e, cudaEventDisableTiming); return e; }();
    static cudaEvent_t ev_h = [] {
        cudaEvent_t e; cudaEventCreateWithFlags(&e, cudaEventDisableTiming); return e; }();

    // fork: build_dir on s1 parallel with wexp on stream 0
    cudaEventRecord(ev_fork, 0);
    cudaStreamWaitEvent(s1, ev_fork, 0);
    wexp_all_kernel<<<4608, 256>>>(ct_W1, os_W1, os_W2, ds_W1);
    build_dir_kernel<<<NROWS, 128, 0, s1>>>(dec, src, tgt_c, type_emb);
    cudaEventRecord(ev_bd, s1);
    cudaStreamWaitEvent(0, ev_bd, 0);

    // fused ds + os1 + ct hidden GEMMs
    gemm_fused3<<<768, 256, GEMM_SMEM>>>(ds_b1, os_b1, ct_b1);

    // fork: heads on s1 parallel with (os2 -> logits) on stream 0
    cudaEventRecord(ev_f3, 0);
    cudaStreamWaitEvent(s1, ev_f3, 0);
    heads_kernel<<<2 * NROWS, 256, 0, s1>>>(ct_W2, ct_b2, ds_W2, ds_b2, out_type, out_dir);
    cudaEventRecord(ev_h, s1);

    gemm_os2<<<dim3(4, 64), 256, OS2_SMEM>>>(os_b2);
    logits_kernel<<<dim3(4, 64), 256>>>(src, out_obj);

    // join before return (required for graph capture)
    cudaStreamWaitEvent(0, ev_h, 0);
}

// round 13
// speedup vs baseline: 1.0564x; 1.0564x over previous
#include <cuda_runtime.h>
#include <cuda_fp16.h>
#include <cstdint>

// ===========================================================================
// ConstraintDecoderModel — fp16 mma.sync + bulk-copy pipeline, R12
// (byte-identical resubmission of R11; prior bench died to container infra):
//  * R10 heads redesign (256 blocks x 32 rows, W2 in smem) with the epilogue
//    fixed: no shuffle in divergent branch, no runtime register indexing
//    (R10's illegal-instruction trap). Lane 0 writes all NOUT outputs.
//  * rest identical to R9/R10 (fused3 / os2 64x128 / stream fork).
// ===========================================================================

#define NROWS 4096

// ---------------- scratch (device globals; no allocation allowed) ----------
__device__ __align__(128) __half g_dir [NROWS * 2048];  // blocked, NCh=32
__device__ __align__(128) __half g_h1os[NROWS * 1024];  // blocked, NCh=16
__device__ __align__(128) __half g_h1ct[NROWS * 1024];  // linear fp16
__device__ __align__(128) __half g_h1ds[NROWS * 1024];  // linear fp16
__device__ __align__(128) float  g_ptr [NROWS * 512];   // linear f32
__device__ __align__(128) __half g_w_ct [1024 *  512];  // blocked, NCh=8
__device__ __align__(128) __half g_w_os1[1024 * 1536];  // blocked, NCh=24
__device__ __align__(128) __half g_w_os2[ 512 * 1024];  // blocked, NCh=16
__device__ __align__(128) __half g_w_ds [1024 * 2048];  // blocked, NCh=32

// ---------------- helpers ---------------------------------------------------
__device__ __forceinline__ uint32_t smem_u32(const void* p) {
    uint32_t a;
    asm("{ .reg .u64 t; cvta.to.shared.u64 t, %1; cvt.u32.u64 %0, t; }"
        : "=r"(a) : "l"(p));
    return a;
}
__device__ __forceinline__ void ldsm_x4(uint32_t& r0, uint32_t& r1,
                                        uint32_t& r2, uint32_t& r3, uint32_t addr) {
    asm volatile("ldmatrix.sync.aligned.m8n8.x4.shared.b16 {%0,%1,%2,%3}, [%4];"
                 : "=r"(r0), "=r"(r1), "=r"(r2), "=r"(r3) : "r"(addr));
}
__device__ __forceinline__ void mma_f16(float* d, const uint32_t* a,
                                        uint32_t b0, uint32_t b1) {
    asm volatile(
        "mma.sync.aligned.m16n8k16.row.col.f32.f16.f16.f32 "
        "{%0,%1,%2,%3}, {%4,%5,%6,%7}, {%8,%9}, {%0,%1,%2,%3};"
        : "+f"(d[0]), "+f"(d[1]), "+f"(d[2]), "+f"(d[3])
        : "r"(a[0]), "r"(a[1]), "r"(a[2]), "r"(a[3]), "r"(b0), "r"(b1));
}
#define MBAR_INIT(a, c) \
    asm volatile("mbarrier.init.shared.b64 [%0], %1;" :: "r"((uint32_t)(a)), "r"((uint32_t)(c)) : "memory")
#define MBAR_EXPECT_TX(a, tx) \
    asm volatile("mbarrier.arrive.expect_tx.shared.b64 _, [%0], %1;" :: "r"((uint32_t)(a)), "r"((uint32_t)(tx)) : "memory")
#define MBAR_WAIT_PARITY(addr, par) do { \
    uint32_t _m = (uint32_t)(addr); uint32_t _p = (uint32_t)(par); uint32_t _d; \
    asm volatile("{\n\t.reg .pred p;\n\t" \
        "mbarrier.try_wait.parity.acquire.cta.shared::cta.b64 p, [%1], %2;\n\t" \
        "selp.b32 %0, 1, 0, p;\n\t}" : "=r"(_d) : "r"(_m), "r"(_p) : "memory"); \
    if (!_d) { \
        asm volatile("{\n\t.reg .pred P1;\n\t" \
            "WL_%=:\n\t" \
            "mbarrier.try_wait.parity.acquire.cta.shared::cta.b64 P1, [%0], %1, 0x989680;\n\t" \
            "@P1 bra.uni WD_%=;\n\t" \
            "bra.uni WL_%=;\n\t" \
            "WD_%=:\n\t}" :: "r"(_m), "r"(_p) : "memory"); \
    } } while (0)
#define FENCE_PROXY_ASYNC() asm volatile("fence.proxy.async.shared::cta;" ::: "memory")
__device__ __forceinline__ void bulk_g2s(uint32_t dst, const void* src,
                                         uint32_t bytes, uint32_t mbar) {
    asm volatile(
        "cp.async.bulk.shared::cluster.global.mbarrier::complete_tx::bytes "
        "[%0], [%1], %2, [%3];"
        :: "r"(dst), "l"(src), "r"(bytes), "r"(mbar) : "memory");
}

// swizzle within a 16KB block: row r, 16B-group c (0..7)
__device__ __forceinline__ uint32_t swz(uint32_t r, uint32_t c) {
    return r * 128 + ((c ^ (r & 7)) << 4);
}
__device__ __forceinline__ uint32_t blk_elem(uint32_t r, uint32_t h) {
    return swz(r, h >> 3) + (h & 7) * 2;
}

// ---------------------------------------------------------------------------
// build dir (blocked): row n gets [heads|type|q|r], K=2048, NCh=32.
// ---------------------------------------------------------------------------
__global__ __launch_bounds__(128) void build_dir_kernel(
    const float* __restrict__ dec, const float* __restrict__ src,
    const int* __restrict__ tgt_c, const float* __restrict__ type_emb)
{
    int n = blockIdx.x;
    int b = n & 63;
    int t0 = tgt_c[n * 3 + 0];
    int q  = tgt_c[n * 3 + 1];
    int r  = tgt_c[n * 3 + 2];
    const float* segs[4] = {
        dec + (size_t)n * 512,
        type_emb + (size_t)t0 * 512,
        src + ((size_t)q * 64 + b) * 512,
        src + ((size_t)r * 64 + b) * 512 };
    char* base = (char*)g_dir + (size_t)(n >> 7) * 32 * 16384;
    uint32_t rr = n & 127;
#pragma unroll
    for (int s = 0; s < 4; s++) {
        const float* P = segs[s];
        for (int i = threadIdx.x * 2; i < 512; i += 256) {
            float2 v = *reinterpret_cast<const float2*>(P + i);
            int kk = s * 512 + i;
            char* dst = base + (size_t)(kk >> 6) * 16384 + blk_elem(rr, kk & 63);
            *reinterpret_cast<__half2*>(dst) =
                __halves2half2(__float2half_rn(v.x), __float2half_rn(v.y));
        }
    }
}

// ---------------------------------------------------------------------------
// Merged weight transpose+convert into BLOCKED fp16 layouts.
// ---------------------------------------------------------------------------
__global__ __launch_bounds__(256) void wexp_all_kernel(
    const float* __restrict__ Wct,  const float* __restrict__ Wos1,
    const float* __restrict__ Wos2, const float* __restrict__ Wds)
{
    int g = blockIdx.x;
    const float* W;
    __half* out;
    int K, N, loc, NCh;
    if (g < 512)       { W = Wct;  out = g_w_ct;  K =  512; N = 1024; loc = g;        NCh =  8; }
    else if (g < 2048) { W = Wos1; out = g_w_os1; K = 1536; N = 1024; loc = g - 512;  NCh = 24; }
    else if (g < 2560) { W = Wos2; out = g_w_os2; K = 1024; N =  512; loc = g - 2048; NCh = 16; }
    else               { W = Wds;  out = g_w_ds;  K = 2048; N = 1024; loc = g - 2560; NCh = 32; }
    int nx = N >> 5;
    int n0 = (loc % nx) * 32, k0 = (loc / nx) * 32;

    __shared__ float t[32][33];
    int tx = threadIdx.x & 31;
    int ty = threadIdx.x >> 5;
#pragma unroll
    for (int r = 0; r < 4; r++)
        t[ty + r * 8][tx] = W[(size_t)(k0 + ty + r * 8) * N + n0 + tx];
    __syncthreads();
#pragma unroll
    for (int r = 0; r < 4; r++) {
        int n = n0 + ty + r * 8;
        int k = k0 + tx;
        char* dst = (char*)out +
            (size_t)((n >> 7) * NCh + (k >> 6)) * 16384 + blk_elem(n & 127, k & 63);
        *reinterpret_cast<__half*>(dst) = __float2half_rn(t[tx][ty + r * 8]);
    }
}

// ---------------------------------------------------------------------------
// 128x128 GEMM body (fused3), bulk-copy pipeline, 3x32KB stages.
// outmode 1: fp16 BLOCKED (NCh=ldc/64); 2: fp16 linear.
// ---------------------------------------------------------------------------
#define STAGES 3
#define STAGE_B 32768
#define GEMM_SMEM (STAGES * STAGE_B + 64)

__device__ __forceinline__ void gemm_body(
    const char* __restrict__ Ab, int sA,
    const char* __restrict__ Bb, int sB,
    const float* __restrict__ bias, void* __restrict__ Cout, int ldc,
    int NC, int bmt, int bnt, int outmode, char* smem)
{
    const uint32_t sbase = smem_u32(smem);
    const uint32_t mb = sbase + STAGES * STAGE_B;
    const int tid = threadIdx.x;
    const int wid = tid >> 5;
    const int lane = tid & 31;
    const int wm = (wid & 3) * 32;
    const int wn = (wid >> 2) * 64;

    if (tid == 0) {
#pragma unroll
        for (int s = 0; s < STAGES; s++) MBAR_INIT(mb + 8 * s, 1);
    }
    __syncthreads();
    FENCE_PROXY_ASYNC();

    auto issue = [&](int c) {
        int sl = c % STAGES;
        uint32_t dst = sbase + sl * STAGE_B;
        MBAR_EXPECT_TX(mb + 8 * sl, 32768);
        bulk_g2s(dst,         Ab + (size_t)(bmt * sA + c) * 16384, 16384, mb + 8 * sl);
        bulk_g2s(dst + 16384, Bb + (size_t)(bnt * sB + c) * 16384, 16384, mb + 8 * sl);
    };
    if (tid == 0) { issue(0); issue(1); }

    float acc[2][8][4];
#pragma unroll
    for (int i = 0; i < 2; i++)
#pragma unroll
        for (int j = 0; j < 8; j++)
#pragma unroll
            for (int v = 0; v < 4; v++) acc[i][j][v] = 0.f;

    const int a_r  = lane & 15;
    const int a_cb = lane >> 4;
    const int b_r  = ((lane >> 4) << 3) + (lane & 7);
    const int b_cb = (lane >> 3) & 1;

    for (int c = 0; c < NC; c++) {
        int sl = c % STAGES;
        MBAR_WAIT_PARITY(mb + 8 * sl, (c / STAGES) & 1);
        __syncthreads();
        if (tid == 0 && c + 2 < NC) issue(c + 2);

        uint32_t As = sbase + sl * STAGE_B;
        uint32_t Bs = As + 16384;
#pragma unroll
        for (int ks = 0; ks < 4; ks++) {
            uint32_t a[2][4];
#pragma unroll
            for (int mi = 0; mi < 2; mi++)
                ldsm_x4(a[mi][0], a[mi][1], a[mi][2], a[mi][3],
                        As + swz(wm + mi * 16 + a_r, ks * 2 + a_cb));
            uint32_t b[4][4];
#pragma unroll
            for (int ni = 0; ni < 4; ni++)
                ldsm_x4(b[ni][0], b[ni][1], b[ni][2], b[ni][3],
                        Bs + swz(wn + ni * 16 + b_r, ks * 2 + b_cb));
#pragma unroll
            for (int mi = 0; mi < 2; mi++)
#pragma unroll
                for (int n8 = 0; n8 < 8; n8++)
                    mma_f16(acc[mi][n8], a[mi],
                            b[n8 >> 1][(n8 & 1) * 2], b[n8 >> 1][(n8 & 1) * 2 + 1]);
        }
    }

    const int bm = bmt * 128, bn = bnt * 128;
#pragma unroll
    for (int mi = 0; mi < 2; mi++) {
        int r0 = bm + wm + mi * 16 + (lane >> 2);
#pragma unroll
        for (int n8 = 0; n8 < 8; n8++) {
            int col = bn + wn + n8 * 8 + (lane & 3) * 2;
            float b0 = bias[col], b1 = bias[col + 1];
            float v00 = acc[mi][n8][0] + b0;
            float v01 = acc[mi][n8][1] + b1;
            float v10 = acc[mi][n8][2] + b0;
            float v11 = acc[mi][n8][3] + b1;
            v00 = v00 > 0.f ? v00 : 0.01f * v00;
            v01 = v01 > 0.f ? v01 : 0.01f * v01;
            v10 = v10 > 0.f ? v10 : 0.01f * v10;
            v11 = v11 > 0.f ? v11 : 0.01f * v11;
            if (outmode == 1) {
                int NCh = ldc >> 6;
                char* C = (char*)Cout;
                char* d0 = C + (size_t)((r0 >> 7) * NCh + (col >> 6)) * 16384
                             + blk_elem(r0 & 127, col & 63);
                *reinterpret_cast<__half2*>(d0) =
                    __halves2half2(__float2half_rn(v00), __float2half_rn(v01));
                int r1 = r0 + 8;
                char* d1 = C + (size_t)((r1 >> 7) * NCh + (col >> 6)) * 16384
                             + blk_elem(r1 & 127, col & 63);
                *reinterpret_cast<__half2*>(d1) =
                    __halves2half2(__float2half_rn(v10), __float2half_rn(v11));
            } else {
                __half* C = (__half*)Cout;
                *reinterpret_cast<__half2*>(C + (size_t)r0 * ldc + col) =
                    __halves2half2(__float2half_rn(v00), __float2half_rn(v01));
                *reinterpret_cast<__half2*>(C + (size_t)(r0 + 8) * ldc + col) =
                    __halves2half2(__float2half_rn(v10), __float2half_rn(v11));
            }
        }
    }
}

__global__ __launch_bounds__(256, 2) void gemm_fused3(
    const float* __restrict__ ds_b1,
    const float* __restrict__ os_b1,
    const float* __restrict__ ct_b1)
{
    extern __shared__ char smem[];
    int g = blockIdx.x;
    int id = g >> 8, r = g & 255;
    int bmt = r >> 3, bnt = r & 7;
    if (id == 0)
        gemm_body((const char*)g_dir, 32, (const char*)g_w_ds, 32,
                  ds_b1, g_h1ds, 1024, 32, bmt, bnt, 2, smem);
    else if (id == 1)
        gemm_body((const char*)g_dir, 32, (const char*)g_w_os1, 24,
                  os_b1, g_h1os, 1024, 24, bmt, bnt, 1, smem);
    else
        gemm_body((const char*)g_dir, 32, (const char*)g_w_ct, 8,
                  ct_b1, g_h1ct, 1024, 8, bmt, bnt, 2, smem);
}

// ---------------------------------------------------------------------------
// os2: 64x128 tiles, grid (4, 64) = 256 CTAs, 3 CTAs/SM, no activation.
// ---------------------------------------------------------------------------
#define OS2_STAGE 24576
#define OS2_SMEM (3 * OS2_STAGE + 64)

__global__ __launch_bounds__(256, 3) void gemm_os2(const float* __restrict__ os_b2)
{
    extern __shared__ char smem[];
    const uint32_t sbase = smem_u32(smem);
    const uint32_t mb = sbase + 3 * OS2_STAGE;
    const int tid = threadIdx.x;
    const int wid = tid >> 5;
    const int lane = tid & 31;
    const int wm = (wid & 1) * 32;
    const int wn = (wid >> 1) * 32;
    const int mt = blockIdx.y;
    const int nt = blockIdx.x;
    const int NC = 16;

    const char* Ab = (const char*)g_h1os;
    const char* Bb = (const char*)g_w_os2;

    if (tid == 0) {
#pragma unroll
        for (int s = 0; s < 3; s++) MBAR_INIT(mb + 8 * s, 1);
    }
    __syncthreads();
    FENCE_PROXY_ASYNC();

    auto issue = [&](int c) {
        int sl = c % 3;
        uint32_t dst = sbase + sl * OS2_STAGE;
        MBAR_EXPECT_TX(mb + 8 * sl, 24576);
        bulk_g2s(dst, Ab + (size_t)((mt >> 1) * 16 + c) * 16384 + (mt & 1) * 8192,
                 8192, mb + 8 * sl);
        bulk_g2s(dst + 8192, Bb + (size_t)(nt * 16 + c) * 16384, 16384, mb + 8 * sl);
    };
    if (tid == 0) { issue(0); issue(1); }

    float acc[2][4][4];
#pragma unroll
    for (int i = 0; i < 2; i++)
#pragma unroll
        for (int j = 0; j < 4; j++)
#pragma unroll
            for (int v = 0; v < 4; v++) acc[i][j][v] = 0.f;

    const int a_r  = lane & 15;
    const int a_cb = lane >> 4;
    const int b_r  = ((lane >> 4) << 3) + (lane & 7);
    const int b_cb = (lane >> 3) & 1;

    for (int c = 0; c < NC; c++) {
        int sl = c % 3;
        MBAR_WAIT_PARITY(mb + 8 * sl, (c / 3) & 1);
        __syncthreads();
        if (tid == 0 && c + 2 < NC) issue(c + 2);

        uint32_t As = sbase + sl * OS2_STAGE;
        uint32_t Bs = As + 8192;
#pragma unroll
        for (int ks = 0; ks < 4; ks++) {
            uint32_t a[2][4];
#pragma unroll
            for (int mi = 0; mi < 2; mi++)
                ldsm_x4(a[mi][0], a[mi][1], a[mi][2], a[mi][3],
                        As + swz(wm + mi * 16 + a_r, ks * 2 + a_cb));
            uint32_t b[2][4];
#pragma unroll
            for (int ni = 0; ni < 2; ni++)
                ldsm_x4(b[ni][0], b[ni][1], b[ni][2], b[ni][3],
                        Bs + swz(wn + ni * 16 + b_r, ks * 2 + b_cb));
#pragma unroll
            for (int mi = 0; mi < 2; mi++)
#pragma unroll
                for (int n8 = 0; n8 < 4; n8++)
                    mma_f16(acc[mi][n8], a[mi],
                            b[n8 >> 1][(n8 & 1) * 2], b[n8 >> 1][(n8 & 1) * 2 + 1]);
        }
    }

#pragma unroll
    for (int mi = 0; mi < 2; mi++) {
        int r0 = mt * 64 + wm + mi * 16 + (lane >> 2);
#pragma unroll
        for (int n8 = 0; n8 < 4; n8++) {
            int col = nt * 128 + wn + n8 * 8 + (lane & 3) * 2;
            float b0 = os_b2[col], b1 = os_b2[col + 1];
            g_ptr[(size_t)r0 * 512 + col]           = acc[mi][n8][0] + b0;
            g_ptr[(size_t)r0 * 512 + col + 1]       = acc[mi][n8][1] + b1;
            g_ptr[(size_t)(r0 + 8) * 512 + col]     = acc[mi][n8][2] + b0;
            g_ptr[(size_t)(r0 + 8) * 512 + col + 1] = acc[mi][n8][3] + b1;
        }
    }
}

// ---------------------------------------------------------------------------
// Output heads: 256 blocks (128 ct + 128 ds) x 32 rows.
// W2 staged once per block into smem transposed [c][k]; warp-per-row reduce.
// After the butterfly every lane holds the full sums; lane 0 writes NOUT
// outputs (no divergent shuffle, no dynamic register indexing).
// ---------------------------------------------------------------------------
template<int NOUT>
__device__ __forceinline__ void heads_block(
    const __half* __restrict__ H, const float* __restrict__ W,
    const float* __restrict__ bias, float* __restrict__ out,
    int row0, float (*Ws)[1024])
{
    for (int i = threadIdx.x; i < 1024 * NOUT; i += 256) {
        int k = i / NOUT, c = i % NOUT;
        Ws[c][k] = W[i];
    }
    __syncthreads();

    int warp = threadIdx.x >> 5, lane = threadIdx.x & 31;
#pragma unroll
    for (int rr = 0; rr < 4; rr++) {
        int row = row0 + warp * 4 + rr;
        const __half* h = H + (size_t)row * 1024;
        float acc[NOUT];
#pragma unroll
        for (int c = 0; c < NOUT; c++) acc[c] = 0.f;
#pragma unroll
        for (int it = 0; it < 16; it++) {
            int k = it * 64 + lane * 2;
            __half2 hv = *reinterpret_cast<const __half2*>(h + k);
            float vx = __low2float(hv), vy = __high2float(hv);
#pragma unroll
            for (int c = 0; c < NOUT; c++)
                acc[c] += vx * Ws[c][k] + vy * Ws[c][k + 1];
        }
#pragma unroll
        for (int c = 0; c < NOUT; c++)
#pragma unroll
            for (int off = 16; off > 0; off >>= 1)
                acc[c] += __shfl_xor_sync(0xffffffffu, acc[c], off);
        if (lane == 0) {
#pragma unroll
            for (int c = 0; c < NOUT; c++)
                out[(size_t)row * NOUT + c] = acc[c] + bias[c];
        }
    }
}

__global__ __launch_bounds__(256) void heads_kernel(
    const float* __restrict__ ct_W2, const float* __restrict__ ct_b2,
    const float* __restrict__ ds_W2, const float* __restrict__ ds_b2,
    float* __restrict__ out_type, float* __restrict__ out_dir)
{
    __shared__ float Ws[5][1024];
    int g = blockIdx.x;
    if (g < 128) heads_block<4>(g_h1ct, ct_W2, ct_b2, out_type, g * 32, Ws);
    else         heads_block<5>(g_h1ds, ds_W2, ds_b2, out_dir, (g - 128) * 32, Ws);
}

// ---------------------------------------------------------------------------
// Logits: C[t][s] (per b) = dot(ptr[t*64+b], src_e[s,b]) over 512.
// ---------------------------------------------------------------------------
__global__ __launch_bounds__(256) void logits_kernel(
    const float* __restrict__ src, float* __restrict__ out_obj)
{
    int tq = blockIdx.x;
    int b  = blockIdx.y;
    __shared__ float Ps[32][17];
    __shared__ float Ss[32][68];

    const int tid = threadIdx.x;
    const int ty = tid >> 4;
    const int tx = tid & 15;

    float acc[4] = {0.f, 0.f, 0.f, 0.f};

    for (int k0 = 0; k0 < 512; k0 += 32) {
        if (tid < 128) {
            int tl = tid >> 3, kc = tid & 7;
            float4 v = *reinterpret_cast<const float4*>(
                g_ptr + ((size_t)(tq * 16 + tl) * 64 + b) * 512 + k0 + kc * 4);
            Ps[kc * 4 + 0][tl] = v.x; Ps[kc * 4 + 1][tl] = v.y;
            Ps[kc * 4 + 2][tl] = v.z; Ps[kc * 4 + 3][tl] = v.w;
        }
#pragma unroll
        for (int i = 0; i < 2; i++) {
            int sl = tid + 256 * i;
            int s = sl >> 3, kc = sl & 7;
            float4 v = *reinterpret_cast<const float4*>(
                src + ((size_t)s * 64 + b) * 512 + k0 + kc * 4);
            Ss[kc * 4 + 0][s] = v.x; Ss[kc * 4 + 1][s] = v.y;
            Ss[kc * 4 + 2][s] = v.z; Ss[kc * 4 + 3][s] = v.w;
        }
        __syncthreads();
#pragma unroll
        for (int kk = 0; kk < 32; kk++) {
            float a = Ps[kk][ty];
            float4 br = *reinterpret_cast<const float4*>(&Ss[kk][tx * 4]);
            acc[0] += a * br.x;
            acc[1] += a * br.y;
            acc[2] += a * br.z;
            acc[3] += a * br.w;
        }
        __syncthreads();
    }

    float* crow = out_obj + ((size_t)(tq * 16 + ty) * 64 + b) * 64 + tx * 4;
    *reinterpret_cast<float4*>(crow) = make_float4(acc[0], acc[1], acc[2], acc[3]);
}

// ---------------------------------------------------------------------------
extern "C" void kernel_launch(void* const* d_in, const int* in_sizes, int n_in,
                              void* d_out, int out_size)
{
    const float* dec      = (const float*)d_in[0];
    const float* src      = (const float*)d_in[1];
    const int*   tgt_c    = (const int*)d_in[3];
    const float* type_emb = (const float*)d_in[6];
    const float* ct_W1 = (const float*)d_in[7];
    const float* ct_b1 = (const float*)d_in[8];
    const float* ct_W2 = (const float*)d_in[9];
    const float* ct_b2 = (const float*)d_in[10];
    const float* os_W1 = (const float*)d_in[11];
    const float* os_b1 = (const float*)d_in[12];
    const float* os_W2 = (const float*)d_in[13];
    const float* os_b2 = (const float*)d_in[14];
    const float* ds_W1 = (const float*)d_in[15];
    const float* ds_b1 = (const float*)d_in[16];
    const float* ds_W2 = (const float*)d_in[17];
    const float* ds_b2 = (const float*)d_in[18];

    float* out      = (float*)d_out;
    float* out_type = out;
    float* out_obj  = out + 4096 * 4;
    float* out_dir  = out + 4096 * 4 + 4096 * 64;

    cudaFuncSetAttribute(gemm_fused3, cudaFuncAttributeMaxDynamicSharedMemorySize, GEMM_SMEM);
    cudaFuncSetAttribute(gemm_os2,    cudaFuncAttributeMaxDynamicSharedMemorySize, OS2_SMEM);

    static cudaStream_t s1 = [] {
        cudaStream_t s; cudaStreamCreateWithFlags(&s, cudaStreamNonBlocking); return s; }();
    static cudaEvent_t ev_fork = [] {
        cudaEvent_t e; cudaEventCreateWithFlags(&e, cudaEventDisableTiming); return e; }();
    static cudaEvent_t ev_bd = [] {
        cudaEvent_t e; cudaEventCreateWithFlags(&e, cudaEventDisableTiming); return e; }();
    static cudaEvent_t ev_f3 = [] {
        cudaEvent_t e; cudaEventCreateWithFlags(&e, cudaEventDisableTiming); return e; }();
    static cudaEvent_t ev_h = [] {
        cudaEvent_t e; cudaEventCreateWithFlags(&e, cudaEventDisableTiming); return e; }();

    // fork: build_dir on s1 parallel with wexp on stream 0
    cudaEventRecord(ev_fork, 0);
    cudaStreamWaitEvent(s1, ev_fork, 0);
    wexp_all_kernel<<<4608, 256>>>(ct_W1, os_W1, os_W2, ds_W1);
    build_dir_kernel<<<NROWS, 128, 0, s1>>>(dec, src, tgt_c, type_emb);
    cudaEventRecord(ev_bd, s1);
    cudaStreamWaitEvent(0, ev_bd, 0);

    // fused ds + os1 + ct hidden GEMMs
    gemm_fused3<<<768, 256, GEMM_SMEM>>>(ds_b1, os_b1, ct_b1);

    // fork: heads on s1 parallel with (os2 -> logits) on stream 0
    cudaEventRecord(ev_f3, 0);
    cudaStreamWaitEvent(s1, ev_f3, 0);
    heads_kernel<<<256, 256, 0, s1>>>(ct_W2, ct_b2, ds_W2, ds_b2, out_type, out_dir);
    cudaEventRecord(ev_h, s1);

    gemm_os2<<<dim3(4, 64), 256, OS2_SMEM>>>(os_b2);
    logits_kernel<<<dim3(4, 64), 256>>>(src, out_obj);

    // join before return (required for graph capture)
    cudaStreamWaitEvent(0, ev_h, 0);
}

// round 15
// speedup vs baseline: 1.1205x; 1.0607x over previous
#include <cuda_runtime.h>
#include <cuda_fp16.h>
#include <cstdint>

// ===========================================================================
// ConstraintDecoderModel — fp16 mma.sync + bulk-copy pipeline, R15
// (byte-identical resubmission of R14; prior bench died to container infra):
//  * fused3 split into gemm_os1 (s0) and gemm_dsct (s1): os2/logits no longer
//    wait for the ds long-pole; they fill its tail (false barrier removed).
//  * heads capped at 128 regs (__launch_bounds__(256,2)) — R13 showed 202
//    regs -> occ 12.6% -> 23us for 67 MFLOP.
//  * GEMM bodies / layouts / numerics identical to R13 (rel_err 4.1246e-4).
// ===========================================================================

#define NROWS 4096

// ---------------- scratch (device globals; no allocation allowed) ----------
__device__ __align__(128) __half g_dir [NROWS * 2048];  // blocked, NCh=32
__device__ __align__(128) __half g_h1os[NROWS * 1024];  // blocked, NCh=16
__device__ __align__(128) __half g_h1ct[NROWS * 1024];  // linear fp16
__device__ __align__(128) __half g_h1ds[NROWS * 1024];  // linear fp16
__device__ __align__(128) float  g_ptr [NROWS * 512];   // linear f32
__device__ __align__(128) __half g_w_ct [1024 *  512];  // blocked, NCh=8
__device__ __align__(128) __half g_w_os1[1024 * 1536];  // blocked, NCh=24
__device__ __align__(128) __half g_w_os2[ 512 * 1024];  // blocked, NCh=16
__device__ __align__(128) __half g_w_ds [1024 * 2048];  // blocked, NCh=32

// ---------------- helpers ---------------------------------------------------
__device__ __forceinline__ uint32_t smem_u32(const void* p) {
    uint32_t a;
    asm("{ .reg .u64 t; cvta.to.shared.u64 t, %1; cvt.u32.u64 %0, t; }"
        : "=r"(a) : "l"(p));
    return a;
}
__device__ __forceinline__ void ldsm_x4(uint32_t& r0, uint32_t& r1,
                                        uint32_t& r2, uint32_t& r3, uint32_t addr) {
    asm volatile("ldmatrix.sync.aligned.m8n8.x4.shared.b16 {%0,%1,%2,%3}, [%4];"
                 : "=r"(r0), "=r"(r1), "=r"(r2), "=r"(r3) : "r"(addr));
}
__device__ __forceinline__ void mma_f16(float* d, const uint32_t* a,
                                        uint32_t b0, uint32_t b1) {
    asm volatile(
        "mma.sync.aligned.m16n8k16.row.col.f32.f16.f16.f32 "
        "{%0,%1,%2,%3}, {%4,%5,%6,%7}, {%8,%9}, {%0,%1,%2,%3};"
        : "+f"(d[0]), "+f"(d[1]), "+f"(d[2]), "+f"(d[3])
        : "r"(a[0]), "r"(a[1]), "r"(a[2]), "r"(a[3]), "r"(b0), "r"(b1));
}
#define MBAR_INIT(a, c) \
    asm volatile("mbarrier.init.shared.b64 [%0], %1;" :: "r"((uint32_t)(a)), "r"((uint32_t)(c)) : "memory")
#define MBAR_EXPECT_TX(a, tx) \
    asm volatile("mbarrier.arrive.expect_tx.shared.b64 _, [%0], %1;" :: "r"((uint32_t)(a)), "r"((uint32_t)(tx)) : "memory")
#define MBAR_WAIT_PARITY(addr, par) do { \
    uint32_t _m = (uint32_t)(addr); uint32_t _p = (uint32_t)(par); uint32_t _d; \
    asm volatile("{\n\t.reg .pred p;\n\t" \
        "mbarrier.try_wait.parity.acquire.cta.shared::cta.b64 p, [%1], %2;\n\t" \
        "selp.b32 %0, 1, 0, p;\n\t}" : "=r"(_d) : "r"(_m), "r"(_p) : "memory"); \
    if (!_d) { \
        asm volatile("{\n\t.reg .pred P1;\n\t" \
            "WL_%=:\n\t" \
            "mbarrier.try_wait.parity.acquire.cta.shared::cta.b64 P1, [%0], %1, 0x989680;\n\t" \
            "@P1 bra.uni WD_%=;\n\t" \
            "bra.uni WL_%=;\n\t" \
            "WD_%=:\n\t}" :: "r"(_m), "r"(_p) : "memory"); \
    } } while (0)
#define FENCE_PROXY_ASYNC() asm volatile("fence.proxy.async.shared::cta;" ::: "memory")
__device__ __forceinline__ void bulk_g2s(uint32_t dst, const void* src,
                                         uint32_t bytes, uint32_t mbar) {
    asm volatile(
        "cp.async.bulk.shared::cluster.global.mbarrier::complete_tx::bytes "
        "[%0], [%1], %2, [%3];"
        :: "r"(dst), "l"(src), "r"(bytes), "r"(mbar) : "memory");
}

// swizzle within a 16KB block: row r, 16B-group c (0..7)
__device__ __forceinline__ uint32_t swz(uint32_t r, uint32_t c) {
    return r * 128 + ((c ^ (r & 7)) << 4);
}
__device__ __forceinline__ uint32_t blk_elem(uint32_t r, uint32_t h) {
    return swz(r, h >> 3) + (h & 7) * 2;
}

// ---------------------------------------------------------------------------
// build dir (blocked): row n gets [heads|type|q|r], K=2048, NCh=32.
// ---------------------------------------------------------------------------
__global__ __launch_bounds__(128) void build_dir_kernel(
    const float* __restrict__ dec, const float* __restrict__ src,
    const int* __restrict__ tgt_c, const float* __restrict__ type_emb)
{
    int n = blockIdx.x;
    int b = n & 63;
    int t0 = tgt_c[n * 3 + 0];
    int q  = tgt_c[n * 3 + 1];
    int r  = tgt_c[n * 3 + 2];
    const float* segs[4] = {
        dec + (size_t)n * 512,
        type_emb + (size_t)t0 * 512,
        src + ((size_t)q * 64 + b) * 512,
        src + ((size_t)r * 64 + b) * 512 };
    char* base = (char*)g_dir + (size_t)(n >> 7) * 32 * 16384;
    uint32_t rr = n & 127;
#pragma unroll
    for (int s = 0; s < 4; s++) {
        const float* P = segs[s];
        for (int i = threadIdx.x * 2; i < 512; i += 256) {
            float2 v = *reinterpret_cast<const float2*>(P + i);
            int kk = s * 512 + i;
            char* dst = base + (size_t)(kk >> 6) * 16384 + blk_elem(rr, kk & 63);
            *reinterpret_cast<__half2*>(dst) =
                __halves2half2(__float2half_rn(v.x), __float2half_rn(v.y));
        }
    }
}

// ---------------------------------------------------------------------------
// Merged weight transpose+convert into BLOCKED fp16 layouts.
// ---------------------------------------------------------------------------
__global__ __launch_bounds__(256) void wexp_all_kernel(
    const float* __restrict__ Wct,  const float* __restrict__ Wos1,
    const float* __restrict__ Wos2, const float* __restrict__ Wds)
{
    int g = blockIdx.x;
    const float* W;
    __half* out;
    int K, N, loc, NCh;
    if (g < 512)       { W = Wct;  out = g_w_ct;  K =  512; N = 1024; loc = g;        NCh =  8; }
    else if (g < 2048) { W = Wos1; out = g_w_os1; K = 1536; N = 1024; loc = g - 512;  NCh = 24; }
    else if (g < 2560) { W = Wos2; out = g_w_os2; K = 1024; N =  512; loc = g - 2048; NCh = 16; }
    else               { W = Wds;  out = g_w_ds;  K = 2048; N = 1024; loc = g - 2560; NCh = 32; }
    int nx = N >> 5;
    int n0 = (loc % nx) * 32, k0 = (loc / nx) * 32;

    __shared__ float t[32][33];
    int tx = threadIdx.x & 31;
    int ty = threadIdx.x >> 5;
#pragma unroll
    for (int r = 0; r < 4; r++)
        t[ty + r * 8][tx] = W[(size_t)(k0 + ty + r * 8) * N + n0 + tx];
    __syncthreads();
#pragma unroll
    for (int r = 0; r < 4; r++) {
        int n = n0 + ty + r * 8;
        int k = k0 + tx;
        char* dst = (char*)out +
            (size_t)((n >> 7) * NCh + (k >> 6)) * 16384 + blk_elem(n & 127, k & 63);
        *reinterpret_cast<__half*>(dst) = __float2half_rn(t[tx][ty + r * 8]);
    }
}

// ---------------------------------------------------------------------------
// 128x128 GEMM body, bulk-copy pipeline, 3x32KB stages.
// outmode 1: fp16 BLOCKED (NCh=ldc/64); 2: fp16 linear.
// ---------------------------------------------------------------------------
#define STAGES 3
#define STAGE_B 32768
#define GEMM_SMEM (STAGES * STAGE_B + 64)

__device__ __forceinline__ void gemm_body(
    const char* __restrict__ Ab, int sA,
    const char* __restrict__ Bb, int sB,
    const float* __restrict__ bias, void* __restrict__ Cout, int ldc,
    int NC, int bmt, int bnt, int outmode, char* smem)
{
    const uint32_t sbase = smem_u32(smem);
    const uint32_t mb = sbase + STAGES * STAGE_B;
    const int tid = threadIdx.x;
    const int wid = tid >> 5;
    const int lane = tid & 31;
    const int wm = (wid & 3) * 32;
    const int wn = (wid >> 2) * 64;

    if (tid == 0) {
#pragma unroll
        for (int s = 0; s < STAGES; s++) MBAR_INIT(mb + 8 * s, 1);
    }
    __syncthreads();
    FENCE_PROXY_ASYNC();

    auto issue = [&](int c) {
        int sl = c % STAGES;
        uint32_t dst = sbase + sl * STAGE_B;
        MBAR_EXPECT_TX(mb + 8 * sl, 32768);
        bulk_g2s(dst,         Ab + (size_t)(bmt * sA + c) * 16384, 16384, mb + 8 * sl);
        bulk_g2s(dst + 16384, Bb + (size_t)(bnt * sB + c) * 16384, 16384, mb + 8 * sl);
    };
    if (tid == 0) { issue(0); issue(1); }

    float acc[2][8][4];
#pragma unroll
    for (int i = 0; i < 2; i++)
#pragma unroll
        for (int j = 0; j < 8; j++)
#pragma unroll
            for (int v = 0; v < 4; v++) acc[i][j][v] = 0.f;

    const int a_r  = lane & 15;
    const int a_cb = lane >> 4;
    const int b_r  = ((lane >> 4) << 3) + (lane & 7);
    const int b_cb = (lane >> 3) & 1;

    for (int c = 0; c < NC; c++) {
        int sl = c % STAGES;
        MBAR_WAIT_PARITY(mb + 8 * sl, (c / STAGES) & 1);
        __syncthreads();
        if (tid == 0 && c + 2 < NC) issue(c + 2);

        uint32_t As = sbase + sl * STAGE_B;
        uint32_t Bs = As + 16384;
#pragma unroll
        for (int ks = 0; ks < 4; ks++) {
            uint32_t a[2][4];
#pragma unroll
            for (int mi = 0; mi < 2; mi++)
                ldsm_x4(a[mi][0], a[mi][1], a[mi][2], a[mi][3],
                        As + swz(wm + mi * 16 + a_r, ks * 2 + a_cb));
            uint32_t b[4][4];
#pragma unroll
            for (int ni = 0; ni < 4; ni++)
                ldsm_x4(b[ni][0], b[ni][1], b[ni][2], b[ni][3],
                        Bs + swz(wn + ni * 16 + b_r, ks * 2 + b_cb));
#pragma unroll
            for (int mi = 0; mi < 2; mi++)
#pragma unroll
                for (int n8 = 0; n8 < 8; n8++)
                    mma_f16(acc[mi][n8], a[mi],
                            b[n8 >> 1][(n8 & 1) * 2], b[n8 >> 1][(n8 & 1) * 2 + 1]);
        }
    }

    const int bm = bmt * 128, bn = bnt * 128;
#pragma unroll
    for (int mi = 0; mi < 2; mi++) {
        int r0 = bm + wm + mi * 16 + (lane >> 2);
#pragma unroll
        for (int n8 = 0; n8 < 8; n8++) {
            int col = bn + wn + n8 * 8 + (lane & 3) * 2;
            float b0 = bias[col], b1 = bias[col + 1];
            float v00 = acc[mi][n8][0] + b0;
            float v01 = acc[mi][n8][1] + b1;
            float v10 = acc[mi][n8][2] + b0;
            float v11 = acc[mi][n8][3] + b1;
            v00 = v00 > 0.f ? v00 : 0.01f * v00;
            v01 = v01 > 0.f ? v01 : 0.01f * v01;
            v10 = v10 > 0.f ? v10 : 0.01f * v10;
            v11 = v11 > 0.f ? v11 : 0.01f * v11;
            if (outmode == 1) {
                int NCh = ldc >> 6;
                char* C = (char*)Cout;
                char* d0 = C + (size_t)((r0 >> 7) * NCh + (col >> 6)) * 16384
                             + blk_elem(r0 & 127, col & 63);
                *reinterpret_cast<__half2*>(d0) =
                    __halves2half2(__float2half_rn(v00), __float2half_rn(v01));
                int r1 = r0 + 8;
                char* d1 = C + (size_t)((r1 >> 7) * NCh + (col >> 6)) * 16384
                             + blk_elem(r1 & 127, col & 63);
                *reinterpret_cast<__half2*>(d1) =
                    __halves2half2(__float2half_rn(v10), __float2half_rn(v11));
            } else {
                __half* C = (__half*)Cout;
                *reinterpret_cast<__half2*>(C + (size_t)r0 * ldc + col) =
                    __halves2half2(__float2half_rn(v00), __float2half_rn(v01));
                *reinterpret_cast<__half2*>(C + (size_t)(r0 + 8) * ldc + col) =
                    __halves2half2(__float2half_rn(v10), __float2half_rn(v11));
            }
        }
    }
}

// os1 GEMM alone (stream 0): feeds os2 ASAP.
__global__ __launch_bounds__(256, 2) void gemm_os1(const float* __restrict__ os_b1)
{
    extern __shared__ char smem[];
    int r = blockIdx.x;
    gemm_body((const char*)g_dir, 32, (const char*)g_w_os1, 24,
              os_b1, g_h1os, 1024, 24, r >> 3, r & 7, 1, smem);
}

// ds + ct GEMMs (stream 1): feed heads.
__global__ __launch_bounds__(256, 2) void gemm_dsct(
    const float* __restrict__ ds_b1, const float* __restrict__ ct_b1)
{
    extern __shared__ char smem[];
    int g = blockIdx.x;
    int id = g >> 8, r = g & 255;
    int bmt = r >> 3, bnt = r & 7;
    if (id == 0)
        gemm_body((const char*)g_dir, 32, (const char*)g_w_ds, 32,
                  ds_b1, g_h1ds, 1024, 32, bmt, bnt, 2, smem);
    else
        gemm_body((const char*)g_dir, 32, (const char*)g_w_ct, 8,
                  ct_b1, g_h1ct, 1024, 8, bmt, bnt, 2, smem);
}

// ---------------------------------------------------------------------------
// os2: 64x128 tiles, grid (4, 64) = 256 CTAs, 3 CTAs/SM, no activation.
// ---------------------------------------------------------------------------
#define OS2_STAGE 24576
#define OS2_SMEM (3 * OS2_STAGE + 64)

__global__ __launch_bounds__(256, 3) void gemm_os2(const float* __restrict__ os_b2)
{
    extern __shared__ char smem[];
    const uint32_t sbase = smem_u32(smem);
    const uint32_t mb = sbase + 3 * OS2_STAGE;
    const int tid = threadIdx.x;
    const int wid = tid >> 5;
    const int lane = tid & 31;
    const int wm = (wid & 1) * 32;
    const int wn = (wid >> 1) * 32;
    const int mt = blockIdx.y;
    const int nt = blockIdx.x;
    const int NC = 16;

    const char* Ab = (const char*)g_h1os;
    const char* Bb = (const char*)g_w_os2;

    if (tid == 0) {
#pragma unroll
        for (int s = 0; s < 3; s++) MBAR_INIT(mb + 8 * s, 1);
    }
    __syncthreads();
    FENCE_PROXY_ASYNC();

    auto issue = [&](int c) {
        int sl = c % 3;
        uint32_t dst = sbase + sl * OS2_STAGE;
        MBAR_EXPECT_TX(mb + 8 * sl, 24576);
        bulk_g2s(dst, Ab + (size_t)((mt >> 1) * 16 + c) * 16384 + (mt & 1) * 8192,
                 8192, mb + 8 * sl);
        bulk_g2s(dst + 8192, Bb + (size_t)(nt * 16 + c) * 16384, 16384, mb + 8 * sl);
    };
    if (tid == 0) { issue(0); issue(1); }

    float acc[2][4][4];
#pragma unroll
    for (int i = 0; i < 2; i++)
#pragma unroll
        for (int j = 0; j < 4; j++)
#pragma unroll
            for (int v = 0; v < 4; v++) acc[i][j][v] = 0.f;

    const int a_r  = lane & 15;
    const int a_cb = lane >> 4;
    const int b_r  = ((lane >> 4) << 3) + (lane & 7);
    const int b_cb = (lane >> 3) & 1;

    for (int c = 0; c < NC; c++) {
        int sl = c % 3;
        MBAR_WAIT_PARITY(mb + 8 * sl, (c / 3) & 1);
        __syncthreads();
        if (tid == 0 && c + 2 < NC) issue(c + 2);

        uint32_t As = sbase + sl * OS2_STAGE;
        uint32_t Bs = As + 8192;
#pragma unroll
        for (int ks = 0; ks < 4; ks++) {
            uint32_t a[2][4];
#pragma unroll
            for (int mi = 0; mi < 2; mi++)
                ldsm_x4(a[mi][0], a[mi][1], a[mi][2], a[mi][3],
                        As + swz(wm + mi * 16 + a_r, ks * 2 + a_cb));
            uint32_t b[2][4];
#pragma unroll
            for (int ni = 0; ni < 2; ni++)
                ldsm_x4(b[ni][0], b[ni][1], b[ni][2], b[ni][3],
                        Bs + swz(wn + ni * 16 + b_r, ks * 2 + b_cb));
#pragma unroll
            for (int mi = 0; mi < 2; mi++)
#pragma unroll
                for (int n8 = 0; n8 < 4; n8++)
                    mma_f16(acc[mi][n8], a[mi],
                            b[n8 >> 1][(n8 & 1) * 2], b[n8 >> 1][(n8 & 1) * 2 + 1]);
        }
    }

#pragma unroll
    for (int mi = 0; mi < 2; mi++) {
        int r0 = mt * 64 + wm + mi * 16 + (lane >> 2);
#pragma unroll
        for (int n8 = 0; n8 < 4; n8++) {
            int col = nt * 128 + wn + n8 * 8 + (lane & 3) * 2;
            float b0 = os_b2[col], b1 = os_b2[col + 1];
            g_ptr[(size_t)r0 * 512 + col]           = acc[mi][n8][0] + b0;
            g_ptr[(size_t)r0 * 512 + col + 1]       = acc[mi][n8][1] + b1;
            g_ptr[(size_t)(r0 + 8) * 512 + col]     = acc[mi][n8][2] + b0;
            g_ptr[(size_t)(r0 + 8) * 512 + col + 1] = acc[mi][n8][3] + b1;
        }
    }
}

// ---------------------------------------------------------------------------
// Output heads: 256 blocks (128 ct + 128 ds) x 32 rows; regs capped for occ 2.
// ---------------------------------------------------------------------------
template<int NOUT>
__device__ __forceinline__ void heads_block(
    const __half* __restrict__ H, const float* __restrict__ W,
    const float* __restrict__ bias, float* __restrict__ out,
    int row0, float (*Ws)[1024])
{
    for (int i = threadIdx.x; i < 1024 * NOUT; i += 256) {
        int k = i / NOUT, c = i % NOUT;
        Ws[c][k] = W[i];
    }
    __syncthreads();

    int warp = threadIdx.x >> 5, lane = threadIdx.x & 31;
#pragma unroll
    for (int rr = 0; rr < 4; rr++) {
        int row = row0 + warp * 4 + rr;
        const __half* h = H + (size_t)row * 1024;
        float acc[NOUT];
#pragma unroll
        for (int c = 0; c < NOUT; c++) acc[c] = 0.f;
#pragma unroll 4
        for (int it = 0; it < 16; it++) {
            int k = it * 64 + lane * 2;
            __half2 hv = *reinterpret_cast<const __half2*>(h + k);
            float vx = __low2float(hv), vy = __high2float(hv);
#pragma unroll
            for (int c = 0; c < NOUT; c++)
                acc[c] += vx * Ws[c][k] + vy * Ws[c][k + 1];
        }
#pragma unroll
        for (int c = 0; c < NOUT; c++)
#pragma unroll
            for (int off = 16; off > 0; off >>= 1)
                acc[c] += __shfl_xor_sync(0xffffffffu, acc[c], off);
        if (lane == 0) {
#pragma unroll
            for (int c = 0; c < NOUT; c++)
                out[(size_t)row * NOUT + c] = acc[c] + bias[c];
        }
    }
}

__global__ __launch_bounds__(256, 2) void heads_kernel(
    const float* __restrict__ ct_W2, const float* __restrict__ ct_b2,
    const float* __restrict__ ds_W2, const float* __restrict__ ds_b2,
    float* __restrict__ out_type, float* __restrict__ out_dir)
{
    __shared__ float Ws[5][1024];
    int g = blockIdx.x;
    if (g < 128) heads_block<4>(g_h1ct, ct_W2, ct_b2, out_type, g * 32, Ws);
    else         heads_block<5>(g_h1ds, ds_W2, ds_b2, out_dir, (g - 128) * 32, Ws);
}

// ---------------------------------------------------------------------------
// Logits: C[t][s] (per b) = dot(ptr[t*64+b], src_e[s,b]) over 512.
// ---------------------------------------------------------------------------
__global__ __launch_bounds__(256) void logits_kernel(
    const float* __restrict__ src, float* __restrict__ out_obj)
{
    int tq = blockIdx.x;
    int b  = blockIdx.y;
    __shared__ float Ps[32][17];
    __shared__ float Ss[32][68];

    const int tid = threadIdx.x;
    const int ty = tid >> 4;
    const int tx = tid & 15;

    float acc[4] = {0.f, 0.f, 0.f, 0.f};

    for (int k0 = 0; k0 < 512; k0 += 32) {
        if (tid < 128) {
            int tl = tid >> 3, kc = tid & 7;
            float4 v = *reinterpret_cast<const float4*>(
                g_ptr + ((size_t)(tq * 16 + tl) * 64 + b) * 512 + k0 + kc * 4);
            Ps[kc * 4 + 0][tl] = v.x; Ps[kc * 4 + 1][tl] = v.y;
            Ps[kc * 4 + 2][tl] = v.z; Ps[kc * 4 + 3][tl] = v.w;
        }
#pragma unroll
        for (int i = 0; i < 2; i++) {
            int sl = tid + 256 * i;
            int s = sl >> 3, kc = sl & 7;
            float4 v = *reinterpret_cast<const float4*>(
                src + ((size_t)s * 64 + b) * 512 + k0 + kc * 4);
            Ss[kc * 4 + 0][s] = v.x; Ss[kc * 4 + 1][s] = v.y;
            Ss[kc * 4 + 2][s] = v.z; Ss[kc * 4 + 3][s] = v.w;
        }
        __syncthreads();
#pragma unroll
        for (int kk = 0; kk < 32; kk++) {
            float a = Ps[kk][ty];
            float4 br = *reinterpret_cast<const float4*>(&Ss[kk][tx * 4]);
            acc[0] += a * br.x;
            acc[1] += a * br.y;
            acc[2] += a * br.z;
            acc[3] += a * br.w;
        }
        __syncthreads();
    }

    float* crow = out_obj + ((size_t)(tq * 16 + ty) * 64 + b) * 64 + tx * 4;
    *reinterpret_cast<float4*>(crow) = make_float4(acc[0], acc[1], acc[2], acc[3]);
}

// ---------------------------------------------------------------------------
extern "C" void kernel_launch(void* const* d_in, const int* in_sizes, int n_in,
                              void* d_out, int out_size)
{
    const float* dec      = (const float*)d_in[0];
    const float* src      = (const float*)d_in[1];
    const int*   tgt_c    = (const int*)d_in[3];
    const float* type_emb = (const float*)d_in[6];
    const float* ct_W1 = (const float*)d_in[7];
    const float* ct_b1 = (const float*)d_in[8];
    const float* ct_W2 = (const float*)d_in[9];
    const float* ct_b2 = (const float*)d_in[10];
    const float* os_W1 = (const float*)d_in[11];
    const float* os_b1 = (const float*)d_in[12];
    const float* os_W2 = (const float*)d_in[13];
    const float* os_b2 = (const float*)d_in[14];
    const float* ds_W1 = (const float*)d_in[15];
    const float* ds_b1 = (const float*)d_in[16];
    const float* ds_W2 = (const float*)d_in[17];
    const float* ds_b2 = (const float*)d_in[18];

    float* out      = (float*)d_out;
    float* out_type = out;
    float* out_obj  = out + 4096 * 4;
    float* out_dir  = out + 4096 * 4 + 4096 * 64;

    cudaFuncSetAttribute(gemm_os1,  cudaFuncAttributeMaxDynamicSharedMemorySize, GEMM_SMEM);
    cudaFuncSetAttribute(gemm_dsct, cudaFuncAttributeMaxDynamicSharedMemorySize, GEMM_SMEM);
    cudaFuncSetAttribute(gemm_os2,  cudaFuncAttributeMaxDynamicSharedMemorySize, OS2_SMEM);

    static cudaStream_t s1 = [] {
        cudaStream_t s; cudaStreamCreateWithFlags(&s, cudaStreamNonBlocking); return s; }();
    static cudaEvent_t ev_fork = [] {
        cudaEvent_t e; cudaEventCreateWithFlags(&e, cudaEventDisableTiming); return e; }();
    static cudaEvent_t ev_bd = [] {
        cudaEvent_t e; cudaEventCreateWithFlags(&e, cudaEventDisableTiming); return e; }();
    static cudaEvent_t ev_prep = [] {
        cudaEvent_t e; cudaEventCreateWithFlags(&e, cudaEventDisableTiming); return e; }();
    static cudaEvent_t ev_h = [] {
        cudaEvent_t e; cudaEventCreateWithFlags(&e, cudaEventDisableTiming); return e; }();

    // prep fork: build_dir on s1 parallel with wexp on stream 0; join on 0.
    cudaEventRecord(ev_fork, 0);
    cudaStreamWaitEvent(s1, ev_fork, 0);
    wexp_all_kernel<<<4608, 256>>>(ct_W1, os_W1, os_W2, ds_W1);
    build_dir_kernel<<<NROWS, 128, 0, s1>>>(dec, src, tgt_c, type_emb);
    cudaEventRecord(ev_bd, s1);
    cudaStreamWaitEvent(0, ev_bd, 0);
    cudaEventRecord(ev_prep, 0);
    cudaStreamWaitEvent(s1, ev_prep, 0);

    // stream 0: os chain (os1 -> os2 -> logits)
    gemm_os1<<<256, 256, GEMM_SMEM>>>(os_b1);
    gemm_os2<<<dim3(4, 64), 256, OS2_SMEM>>>(os_b2);
    logits_kernel<<<dim3(4, 64), 256>>>(src, out_obj);

    // stream 1: ds+ct -> heads
    gemm_dsct<<<512, 256, GEMM_SMEM, s1>>>(ds_b1, ct_b1);
    heads_kernel<<<256, 256, 0, s1>>>(ct_W2, ct_b2, ds_W2, ds_b2, out_type, out_dir);
    cudaEventRecord(ev_h, s1);

    // join before return (required for graph capture)
    cudaStreamWaitEvent(0, ev_h, 0);
}